// round 9
// baseline (speedup 1.0000x reference)
#include <cuda_runtime.h>

#define Bq 16
#define Sq 128
#define Dq 300
#define Oq 64
#define Eq 16
#define Tq 45
#define TP 48               // padded type count
#define ROWS_TOT 2048
#define WROW 316
#define KT 60               // K-chunk
#define CST 68              // smem col stride (floats): 272B, 16B-aligned, 4-bank lane stride
#define WBUF (64*CST)       // per-buffer stride (max 64 cols)

// __device__ scratch (allocation-free rule)
__device__ float g_ht[ROWS_TOT*Oq];
__device__ float g_E [ROWS_TOT*TP];
__device__ float g_U1[Tq*Oq];
__device__ float g_U2[Tq*Oq];
__device__ float g_e [TP];          // zero-init covers t>=45
__device__ float g_Vt[TP*304];      // V transposed [t][k], rowlen 304

// ---------------------------------------------------------------------------
// cp.async helper
// ---------------------------------------------------------------------------
__device__ __forceinline__ void cp16(float* sdst, const float* gsrc) {
    unsigned a = (unsigned)__cvta_generic_to_shared(sdst);
    asm volatile("cp.async.cg.shared.global [%0], [%1], 16;" :: "r"(a), "l"(gsrc));
}

// ---------------------------------------------------------------------------
// K0a: U1/U2 = dep-type embedding folded through W1/W2 tails;
//      e[t] = b1·U2[t] + b2·U1[t] + U1[t]·U2[t].   45 blocks x 64 threads.
// ---------------------------------------------------------------------------
__global__ void u_kernel(const float* __restrict__ dep_table,
                         const float* __restrict__ W1, const float* __restrict__ b1,
                         const float* __restrict__ W2, const float* __restrict__ b2) {
    __shared__ float sdt[Eq];
    __shared__ float swp[2];
    int t = blockIdx.x, o = threadIdx.x;
    if (o < Eq) sdt[o] = dep_table[t*Eq + o];
    __syncthreads();
    float s1 = 0.f, s2 = 0.f;
    #pragma unroll
    for (int e = 0; e < Eq; e++) {
        float de = sdt[e];
        s1 += __ldg(&W1[o*WROW + Dq + e]) * de;
        s2 += __ldg(&W2[o*WROW + Dq + e]) * de;
    }
    g_U1[t*Oq + o] = s1;
    g_U2[t*Oq + o] = s2;
    float v = b1[o]*s2 + b2[o]*s1 + s1*s2;
    #pragma unroll
    for (int off = 16; off; off >>= 1) v += __shfl_xor_sync(0xffffffffu, v, off);
    if ((o & 31) == 0) swp[o >> 5] = v;
    __syncthreads();
    if (o == 0) g_e[t] = swp[0] + swp[1];
}

// ---------------------------------------------------------------------------
// K0b: V[t][k] = sum_o W1[o][k]*U2[t][o] + W2[o][k]*U1[t][o]  -> g_Vt[t][k].
//      75 blocks x 192 threads (4 k x 48 t). Reads U from global (after K0a).
// ---------------------------------------------------------------------------
__global__ void __launch_bounds__(192) v_kernel(const float* __restrict__ W1,
                                                const float* __restrict__ W2) {
    __shared__ float sU1t[Oq*49], sU2t[Oq*49];     // [o][t] pad 49
    __shared__ float sW1c[Oq*4], sW2c[Oq*4];       // [o][kk]
    int tid = threadIdx.x;
    int kbase = blockIdx.x * 4;
    for (int i = tid; i < Tq*Oq; i += 192) {
        int t = i >> 6, o = i & 63;
        sU1t[o*49 + t] = g_U1[i];
        sU2t[o*49 + t] = g_U2[i];
    }
    for (int i = tid; i < Oq*4; i += 192) {
        int o = i >> 2, k = i & 3;
        sW1c[i] = __ldg(&W1[o*WROW + kbase + k]);
        sW2c[i] = __ldg(&W2[o*WROW + kbase + k]);
    }
    __syncthreads();
    int t = tid % TP, kk = tid / TP;
    float acc = 0.f;
    if (t < Tq) {
        #pragma unroll 8
        for (int o = 0; o < Oq; o++)
            acc += sW1c[o*4 + kk] * sU2t[o*49 + t]
                 + sW2c[o*4 + kk] * sU1t[o*49 + t];
    }
    g_Vt[t*304 + kbase + kk] = acc;   // 0 for t>=45
}

// ---------------------------------------------------------------------------
// K1 (gemm): 256 blocks x 256 threads.
//   Type A (bx<128):  16 rows x 64 ht cols (Wg)       -> g_ht
//   Type B (bx>=128): 16 rows x 48 S cols (V) + softmax epilogue -> g_E
//   f32x2 packed row-pair accumulation, double-buffered cp.async staging.
// ---------------------------------------------------------------------------
__global__ void __launch_bounds__(256) gemm_kernel(
        const float* __restrict__ h,
        const float* __restrict__ Wg, const float* __restrict__ bg,
        const unsigned char* __restrict__ mask8) {
    extern __shared__ float sm[];
    float* sh2 = sm;                  // 8 pairs x 300 float2 = 4800 floats
    float* sW  = sm + 4800;           // 2 x WBUF = 8704 floats
    float* ssv = sW;                  // B epilogue alias: 16*48
    float* se  = sW + 16*TP;          // 48
    __shared__ int sp[5];
    __shared__ float swt[16];
    __shared__ float smx[16];

    int tid  = threadIdx.x;
    int bx   = blockIdx.x;
    bool tb  = bx >= 128;             // type B
    int row0 = (bx & 127) * 16;
    int b    = row0 >> 7;
    int ncols = tb ? TP : Oq;

    // ---- aspect span scan (dual bool-dtype robust) ----
    if (tid < 5) sp[tid] = (tid==0 || tid==3) ? Sq : ((tid==1 || tid==4) ? -1 : 0);
    __syncthreads();
    if (tid < 128 && mask8[(b<<7) + tid]) {
        atomicMin(&sp[0], tid); atomicMax(&sp[1], tid); atomicAdd(&sp[2], 1);
    }
    __syncthreads();
    bool valid8 = (sp[2] == 3 && sp[1] - sp[0] == 2);
    if (!valid8) {
        const int* m32 = (const int*)mask8;
        if (tid < 128 && m32[(b<<7) + tid] != 0) {
            atomicMin(&sp[3], tid); atomicMax(&sp[4], tid);
        }
    }
    __syncthreads();
    int st = valid8 ? sp[0] : sp[3];
    int en = valid8 ? sp[1] : sp[4];
    if (tid < 16) {
        int s = (row0 + tid) & 127;
        float w;
        if (s < st)      w = 1.0f - (float)(st - s) * (1.0f/128.0f);
        else if (s > en) w = 1.0f - (float)(s - en) * (1.0f/128.0f);
        else             w = 0.0f;
        swt[tid] = w;
    }
    __syncthreads();

    // ---- stage position-weighted h, packed row pairs: sh2[(p*300+k)*2 + (r&1)] ----
    {
        const float4* h4 = (const float4*)(h + (size_t)row0 * Dq);
        for (int i = tid; i < 16*75; i += 256) {
            int r = i / 75, q = i - r*75;
            float4 v = h4[i];
            float w = swt[r];
            float* dst = sh2 + ((r >> 1)*300 + q*4)*2 + (r & 1);
            dst[0] = v.x*w; dst[2] = v.y*w; dst[4] = v.z*w; dst[6] = v.w*w;
        }
    }

    #define STAGE_CHUNK(buf, cc)                                            \
        for (int i = tid; i < ncols*15; i += 256) {                         \
            int col = i / 15, q = i - col*15;                               \
            const float* src = tb                                           \
                ? g_Vt + (size_t)col * 304 + (cc)*KT + q*4                  \
                : Wg   + (size_t)col * Dq  + (cc)*KT + q*4;                 \
            cp16(&sW[(buf)*WBUF + col*CST + q*4], src);                     \
        }                                                                   \
        asm volatile("cp.async.commit_group;" ::: "memory");

    STAGE_CHUNK(0, 0)

    // thread mapping: cg 0..63 (col) | ph 0..3 (pairs ph*2, ph*2+1)
    int cg = tid & 63;
    int ph = tid >> 6;
    int wcol = (cg < ncols) ? cg : (ncols - 1);    // clamp inside staged window
    unsigned long long acc[2] = {0ull, 0ull};
    const unsigned long long* sh2u = (const unsigned long long*)sh2;

    for (int c = 0; c < 5; c++) {
        if (c < 4) { STAGE_CHUNK((c+1)&1, c+1) }
        if (c < 4) asm volatile("cp.async.wait_group 1;" ::: "memory");
        else       asm volatile("cp.async.wait_group 0;" ::: "memory");
        __syncthreads();

        const float* wp = sW + (c & 1)*WBUF + wcol*CST;
        #pragma unroll 5
        for (int k4 = 0; k4 < 15; k4++) {
            float4 wv = *(const float4*)&wp[k4*4];
            unsigned long long hk[2][4];
            #pragma unroll
            for (int j = 0; j < 2; j++) {
                const unsigned long long* hp =
                    &sh2u[(size_t)(ph*2 + j)*300 + c*KT + k4*4];
                ulonglong2 t0 = *(const ulonglong2*)(hp);
                ulonglong2 t1 = *(const ulonglong2*)(hp + 2);
                hk[j][0] = t0.x; hk[j][1] = t0.y; hk[j][2] = t1.x; hk[j][3] = t1.y;
            }
            #pragma unroll
            for (int kk = 0; kk < 4; kk++) {
                unsigned long long wpk;
                unsigned wu = __float_as_uint(((const float*)&wv)[kk]);
                asm("mov.b64 %0, {%1, %1};" : "=l"(wpk) : "r"(wu));
                #pragma unroll
                for (int j = 0; j < 2; j++)
                    asm("fma.rn.f32x2 %0, %1, %2, %0;"
                        : "+l"(acc[j]) : "l"(hk[j][kk]), "l"(wpk));
            }
        }
        __syncthreads();
    }

    // ---- epilogue ----
    if (!tb) {
        float bt = bg[cg];
        #pragma unroll
        for (int j = 0; j < 2; j++) {
            int r = (ph*2 + j)*2;
            unsigned lo = (unsigned)(acc[j] & 0xffffffffu);
            unsigned hi = (unsigned)(acc[j] >> 32);
            g_ht[(size_t)(row0 + r    )*Oq + cg] = __uint_as_float(lo) + bt;
            g_ht[(size_t)(row0 + r + 1)*Oq + cg] = __uint_as_float(hi) + bt;
        }
        return;
    }

    // type B: score table -> softmax numerators
    if (tid < TP) se[tid] = g_e[tid];
    if (cg < TP) {
        #pragma unroll
        for (int j = 0; j < 2; j++) {
            int r = (ph*2 + j)*2;
            unsigned lo = (unsigned)(acc[j] & 0xffffffffu);
            unsigned hi = (unsigned)(acc[j] >> 32);
            ssv[(r    )*TP + cg] = __uint_as_float(lo);
            ssv[(r + 1)*TP + cg] = __uint_as_float(hi);
        }
    }
    __syncthreads();
    if (tid < 16) {
        float m = -1e30f;
        #pragma unroll 5
        for (int t = 0; t < Tq; t++) m = fmaxf(m, ssv[tid*TP + t] + se[t]);
        smx[tid] = m;
    }
    __syncthreads();
    for (int i = tid; i < 16*TP; i += 256) {
        int r = i / TP, t = i - r*TP;
        float v = (t > 0 && t < Tq) ? __expf((ssv[i] + se[t] - smx[r]) * 0.125f) : 0.f;
        g_E[(size_t)(row0 + r)*TP + t] = v;
    }
    #undef STAGE_CHUNK
}

// ---------------------------------------------------------------------------
// K2 (attn): 512 blocks x 256 threads. Block = (8 rows, o-half of 32).
//   cp.async prefetch of the sht half overlaps the gather/row-sum phase.
// ---------------------------------------------------------------------------
__global__ void __launch_bounds__(256) attn_kernel(
        const int* __restrict__ dep,
        const float* __restrict__ bias,
        float* __restrict__ out) {
    __shared__ float sE[8*TP];
    __shared__ float sht[Sq*32];     // 16 KB: this block's o-half of h_trans
    __shared__ float sA[8*Sq];
    __shared__ float spart[8*4];
    __shared__ float sden[8];

    int tid = threadIdx.x;
    int bx  = blockIdx.x;
    int rg  = bx >> 1, oh = bx & 1;
    int gr0 = rg * 8;
    int b   = gr0 >> 7;

    // prefetch h_trans half (128 rows x 32 floats)
    {
        const float* src = g_ht + ((size_t)b * Sq) * Oq + oh*32;
        for (int i = tid; i < Sq*8; i += 256) {      // 1024 float4
            int u = i >> 3, q = i & 7;
            cp16(&sht[u*32 + q*4], src + (size_t)u*Oq + q*4);
        }
        asm volatile("cp.async.commit_group;" ::: "memory");
    }

    for (int i = tid; i < 8*TP; i += 256) sE[i] = g_E[(size_t)gr0*TP + i];
    __syncthreads();

    int pos = tid & 127, rhh = tid >> 7;
    int wid = tid >> 5, lane = tid & 31;
    #pragma unroll
    for (int rr = 0; rr < 4; rr++) {
        int row = rr*2 + rhh;
        int ty = dep[(size_t)(gr0 + row)*Sq + pos];
        float e = sE[row*TP + ty];
        sA[row*Sq + pos] = e;
        float s = e;
        #pragma unroll
        for (int off = 16; off; off >>= 1)
            s += __shfl_xor_sync(0xffffffffu, s, off);
        if (lane == 0) spart[row*4 + (wid & 3)] = s;
    }
    __syncthreads();
    if (tid < 8)
        sden[tid] = 1.0f / (spart[tid*4] + spart[tid*4+1] +
                            spart[tid*4+2] + spart[tid*4+3] + 1e-6f);
    asm volatile("cp.async.wait_group 0;" ::: "memory");
    __syncthreads();

    // matmul: one warp per row, lane = o within half
    int g = tid >> 5;
    const float* Ar = sA + g*Sq;
    float a = 0.f;
    #pragma unroll 8
    for (int u4 = 0; u4 < 32; u4++) {
        float4 av = *(const float4*)&Ar[u4*4];
        a += av.x * sht[(u4*4+0)*32 + lane]
           + av.y * sht[(u4*4+1)*32 + lane]
           + av.z * sht[(u4*4+2)*32 + lane]
           + av.w * sht[(u4*4+3)*32 + lane];
    }
    float v = a * sden[g] + bias[oh*32 + lane];
    out[(size_t)(gr0 + g)*Oq + oh*32 + lane] = fmaxf(v, 0.f);
}

// ---------------------------------------------------------------------------
// Inputs: h, dep_table, W1, b1, W2, b2, Wg, bg, bias, dep_type_matrix, aspect_mask
// ---------------------------------------------------------------------------
extern "C" void kernel_launch(void* const* d_in, const int* in_sizes, int n_in,
                              void* d_out, int out_size) {
    const float* h         = (const float*)d_in[0];
    const float* dep_table = (const float*)d_in[1];
    const float* W1        = (const float*)d_in[2];
    const float* b1        = (const float*)d_in[3];
    const float* W2        = (const float*)d_in[4];
    const float* b2        = (const float*)d_in[5];
    const float* Wg        = (const float*)d_in[6];
    const float* bg        = (const float*)d_in[7];
    const float* bias      = (const float*)d_in[8];
    const int*   dep       = (const int*)d_in[9];
    const unsigned char* mask = (const unsigned char*)d_in[10];

    const int gemm_smem = (4800 + 2*WBUF) * (int)sizeof(float);   // 54016 B
    cudaFuncSetAttribute(gemm_kernel,
                         cudaFuncAttributeMaxDynamicSharedMemorySize, gemm_smem);

    u_kernel<<<Tq, 64>>>(dep_table, W1, b1, W2, b2);
    v_kernel<<<75, 192>>>(W1, W2);
    gemm_kernel<<<256, 256, gemm_smem>>>(h, Wg, bg, mask);
    attn_kernel<<<512, 256>>>(dep, bias, (float*)d_out);
}

// round 10
// speedup vs baseline: 1.0556x; 1.0556x over previous
#include <cuda_runtime.h>

#define Bq 16
#define Sq 128
#define Dq 300
#define Oq 64
#define Eq 16
#define Tq 45
#define TP 48               // padded type count
#define ROWS_TOT 2048
#define WROW 316
#define KT 60               // K-chunk
#define CST 68              // smem col stride (floats): 272B, 16B-aligned
#define WBUF (64*CST)       // type-A per-buffer stride (64 cols)
#define CBUF (16*CST)       // type-B per-buffer stride (16 cols)

// __device__ scratch (allocation-free rule; zero-initialized)
__device__ float g_ht[ROWS_TOT*Oq];
__device__ float g_E [ROWS_TOT*TP];
__device__ float g_e [TP];          // zero-init covers t>=45
__device__ float g_C [Eq*304];      // C[e][k], rowlen 304

// ---------------------------------------------------------------------------
// cp.async helper
// ---------------------------------------------------------------------------
__device__ __forceinline__ void cp16(float* sdst, const float* gsrc) {
    unsigned a = (unsigned)__cvta_generic_to_shared(sdst);
    asm volatile("cp.async.cg.shared.global [%0], [%1], 16;" :: "r"(a), "l"(gsrc));
}

// ---------------------------------------------------------------------------
// P1: C[e][k] = sum_o W1[o][k]*W2[o][D+e] + W2[o][k]*W1[o][D+e]
//     (75 blocks x 64 threads; block bx handles k = bx*4..bx*4+3).
//     Block 0 also computes cb/Q and e[t] = dt·cb + dtᵀQdt.
// ---------------------------------------------------------------------------
__global__ void __launch_bounds__(64) p1_kernel(
        const float* __restrict__ dep_table,
        const float* __restrict__ W1, const float* __restrict__ b1,
        const float* __restrict__ W2, const float* __restrict__ b2) {
    __shared__ float sWt1[Oq*Eq], sWt2[Oq*Eq];   // tails [o][e]
    __shared__ float sW1c[Oq*4],  sW2c[Oq*4];    // k-cols [o][kk]
    __shared__ float sQ[256], scb[16], sb1[Oq], sb2[Oq];
    int tid = threadIdx.x;                       // 64 threads
    int o = tid;
    int kbase = blockIdx.x * 4;

    #pragma unroll
    for (int q = 0; q < 4; q++) {
        *(float4*)&sWt1[o*Eq + q*4] = *(const float4*)&W1[o*WROW + Dq + q*4];
        *(float4*)&sWt2[o*Eq + q*4] = *(const float4*)&W2[o*WROW + Dq + q*4];
    }
    *(float4*)&sW1c[o*4] = *(const float4*)&W1[o*WROW + kbase];
    *(float4*)&sW2c[o*4] = *(const float4*)&W2[o*WROW + kbase];
    if (blockIdx.x == 0) { sb1[o] = b1[o]; sb2[o] = b2[o]; }
    __syncthreads();

    {
        int e = tid & 15, kk = tid >> 4;
        float acc = 0.f;
        #pragma unroll 8
        for (int oo = 0; oo < Oq; oo++)
            acc += sW1c[oo*4 + kk] * sWt2[oo*Eq + e]
                 + sW2c[oo*4 + kk] * sWt1[oo*Eq + e];
        g_C[e*304 + kbase + kk] = acc;
    }

    if (blockIdx.x == 0) {
        int e = tid & 15, g4 = tid >> 4;
        #pragma unroll
        for (int j = 0; j < 4; j++) {
            int ep = g4*4 + j;
            float q = 0.f;
            #pragma unroll 8
            for (int oo = 0; oo < Oq; oo++)
                q += sWt1[oo*Eq + e] * sWt2[oo*Eq + ep];
            sQ[e*16 + ep] = q;
        }
        if (tid < 16) {
            float c = 0.f;
            #pragma unroll 8
            for (int oo = 0; oo < Oq; oo++)
                c += sb1[oo] * sWt2[oo*Eq + tid] + sb2[oo] * sWt1[oo*Eq + tid];
            scb[tid] = c;
        }
        __syncthreads();
        if (tid < Tq) {
            float dte[Eq];
            #pragma unroll
            for (int e2 = 0; e2 < Eq; e2++) dte[e2] = dep_table[tid*Eq + e2];
            float acc = 0.f;
            #pragma unroll
            for (int e2 = 0; e2 < Eq; e2++) {
                float row = scb[e2];
                #pragma unroll
                for (int e3 = 0; e3 < Eq; e3++)
                    row += sQ[e2*16 + e3] * dte[e3];
                acc += dte[e2] * row;
            }
            g_e[tid] = acc;
        }
    }
}

// ---------------------------------------------------------------------------
// K1 (gemm): 192 blocks x 256 threads.
//   Type A (bx<128):  16 rows x 64 Wg cols -> g_ht
//   Type B (bx>=128): 32 rows x 16 C cols -> y; epilogue S = y·dt + e[t],
//                     row max, exp -> g_E.
// ---------------------------------------------------------------------------
__global__ void __launch_bounds__(256) gemm_kernel(
        const float* __restrict__ h,
        const float* __restrict__ Wg, const float* __restrict__ bg,
        const float* __restrict__ dep_table,
        const unsigned char* __restrict__ mask8) {
    extern __shared__ float sm[];
    __shared__ int sp[5];
    __shared__ float swt[32];
    __shared__ float smx[32];

    int tid  = threadIdx.x;
    int bx   = blockIdx.x;
    bool tb  = bx >= 128;
    int nrows = tb ? 32 : 16;
    int row0 = tb ? (bx - 128) * 32 : bx * 16;
    int b    = row0 >> 7;
    int ncols = tb ? Eq : Oq;

    float* sh2 = sm;
    float* sW  = sm + (tb ? 9600 : 4800);

    // ---- aspect span scan (dual bool-dtype robust) ----
    if (tid < 5) sp[tid] = (tid==0 || tid==3) ? Sq : ((tid==1 || tid==4) ? -1 : 0);
    __syncthreads();
    if (tid < 128 && mask8[(b<<7) + tid]) {
        atomicMin(&sp[0], tid); atomicMax(&sp[1], tid); atomicAdd(&sp[2], 1);
    }
    __syncthreads();
    bool valid8 = (sp[2] == 3 && sp[1] - sp[0] == 2);
    if (!valid8) {
        const int* m32 = (const int*)mask8;
        if (tid < 128 && m32[(b<<7) + tid] != 0) {
            atomicMin(&sp[3], tid); atomicMax(&sp[4], tid);
        }
    }
    __syncthreads();
    int st = valid8 ? sp[0] : sp[3];
    int en = valid8 ? sp[1] : sp[4];
    if (tid < nrows) {
        int s = (row0 + tid) & 127;
        float w;
        if (s < st)      w = 1.0f - (float)(st - s) * (1.0f/128.0f);
        else if (s > en) w = 1.0f - (float)(s - en) * (1.0f/128.0f);
        else             w = 0.0f;
        swt[tid] = w;
    }
    __syncthreads();

    // ---- stage position-weighted h, packed row pairs ----
    {
        const float4* h4 = (const float4*)(h + (size_t)row0 * Dq);
        for (int i = tid; i < nrows*75; i += 256) {
            int r = i / 75, q = i - r*75;
            float4 v = h4[i];
            float w = swt[r];
            float* dst = sh2 + ((r >> 1)*300 + q*4)*2 + (r & 1);
            dst[0] = v.x*w; dst[2] = v.y*w; dst[4] = v.z*w; dst[6] = v.w*w;
        }
    }

    int bufstride = tb ? CBUF : WBUF;
    #define STAGE_CHUNK(buf, cc)                                            \
        for (int i = tid; i < ncols*15; i += 256) {                         \
            int col = i / 15, q = i - col*15;                               \
            const float* src = tb                                           \
                ? g_C + (size_t)col * 304 + (cc)*KT + q*4                   \
                : Wg  + (size_t)col * Dq  + (cc)*KT + q*4;                  \
            cp16(&sW[(buf)*bufstride + col*CST + q*4], src);                \
        }                                                                   \
        asm volatile("cp.async.commit_group;" ::: "memory");

    STAGE_CHUNK(0, 0)
    const unsigned long long* sh2u = (const unsigned long long*)sh2;

    if (!tb) {
        // ---- type A: 16 rows x 64 cols; thread = (col, 2 pairs) ----
        int cg = tid & 63;
        int ph = tid >> 6;
        unsigned long long acc[2] = {0ull, 0ull};
        for (int c = 0; c < 5; c++) {
            if (c < 4) { STAGE_CHUNK((c+1)&1, c+1) }
            if (c < 4) asm volatile("cp.async.wait_group 1;" ::: "memory");
            else       asm volatile("cp.async.wait_group 0;" ::: "memory");
            __syncthreads();
            const float* wp = sW + (c & 1)*WBUF + cg*CST;
            #pragma unroll 5
            for (int k4 = 0; k4 < 15; k4++) {
                float4 wv = *(const float4*)&wp[k4*4];
                unsigned long long hk[2][4];
                #pragma unroll
                for (int j = 0; j < 2; j++) {
                    const unsigned long long* hp =
                        &sh2u[(size_t)(ph*2 + j)*300 + c*KT + k4*4];
                    ulonglong2 t0 = *(const ulonglong2*)(hp);
                    ulonglong2 t1 = *(const ulonglong2*)(hp + 2);
                    hk[j][0] = t0.x; hk[j][1] = t0.y; hk[j][2] = t1.x; hk[j][3] = t1.y;
                }
                #pragma unroll
                for (int kk = 0; kk < 4; kk++) {
                    unsigned long long wpk;
                    unsigned wu = __float_as_uint(((const float*)&wv)[kk]);
                    asm("mov.b64 %0, {%1, %1};" : "=l"(wpk) : "r"(wu));
                    #pragma unroll
                    for (int j = 0; j < 2; j++)
                        asm("fma.rn.f32x2 %0, %1, %2, %0;"
                            : "+l"(acc[j]) : "l"(hk[j][kk]), "l"(wpk));
                }
            }
            __syncthreads();
        }
        float bt = bg[cg];
        #pragma unroll
        for (int j = 0; j < 2; j++) {
            int r = (ph*2 + j)*2;
            unsigned lo = (unsigned)(acc[j] & 0xffffffffu);
            unsigned hi = (unsigned)(acc[j] >> 32);
            g_ht[(size_t)(row0 + r    )*Oq + cg] = __uint_as_float(lo) + bt;
            g_ht[(size_t)(row0 + r + 1)*Oq + cg] = __uint_as_float(hi) + bt;
        }
        return;
    }

    // ---- type B: 32 rows x 16 C cols; thread = (col e, pair p) ----
    {
        int e = tid & 15;
        int p = tid >> 4;          // 0..15 pairs -> rows 2p, 2p+1
        unsigned long long acc = 0ull;
        for (int c = 0; c < 5; c++) {
            if (c < 4) { STAGE_CHUNK((c+1)&1, c+1) }
            if (c < 4) asm volatile("cp.async.wait_group 1;" ::: "memory");
            else       asm volatile("cp.async.wait_group 0;" ::: "memory");
            __syncthreads();
            const float* wp = sW + (c & 1)*CBUF + e*CST;
            #pragma unroll 5
            for (int k4 = 0; k4 < 15; k4++) {
                float4 wv = *(const float4*)&wp[k4*4];
                const unsigned long long* hp =
                    &sh2u[(size_t)p*300 + c*KT + k4*4];
                ulonglong2 t0 = *(const ulonglong2*)(hp);
                ulonglong2 t1 = *(const ulonglong2*)(hp + 2);
                unsigned long long hk[4] = {t0.x, t0.y, t1.x, t1.y};
                #pragma unroll
                for (int kk = 0; kk < 4; kk++) {
                    unsigned long long wpk;
                    unsigned wu = __float_as_uint(((const float*)&wv)[kk]);
                    asm("mov.b64 %0, {%1, %1};" : "=l"(wpk) : "r"(wu));
                    asm("fma.rn.f32x2 %0, %1, %2, %0;"
                        : "+l"(acc) : "l"(hk[kk]), "l"(wpk));
                }
            }
            __syncthreads();
        }

        // epilogue smem (sh2/sW regions dead after last sync)
        float* sy  = sm;            // 32*16
        float* sdt = sm + 1024;     // 45*16
        float* se  = sm + 1792;     // 48
        float* ssv = sm + 2048;     // 32*48

        {
            unsigned lo = (unsigned)(acc & 0xffffffffu);
            unsigned hi = (unsigned)(acc >> 32);
            sy[(p*2    )*16 + e] = __uint_as_float(lo);
            sy[(p*2 + 1)*16 + e] = __uint_as_float(hi);
        }
        for (int i = tid; i < Tq*Eq; i += 256) sdt[i] = dep_table[i];
        if (tid < TP) se[tid] = g_e[tid];
        __syncthreads();

        // S[r][t] = y[r]·dt[t] + e[t]
        for (int i = tid; i < 32*TP; i += 256) {
            int r = i / TP, t = i - r*TP;
            float s;
            if (t < Tq) {
                s = se[t];
                const float* yr = sy + r*16;
                const float* dt = sdt + t*16;
                #pragma unroll
                for (int e2 = 0; e2 < Eq; e2++) s += yr[e2]*dt[e2];
            } else s = -1e30f;
            ssv[i] = s;
        }
        __syncthreads();
        if (tid < 32) {
            float m = -1e30f;
            #pragma unroll 8
            for (int t = 0; t < TP; t++) m = fmaxf(m, ssv[tid*TP + t]);
            smx[tid] = m;
        }
        __syncthreads();
        for (int i = tid; i < 32*TP; i += 256) {
            int r = i / TP, t = i - r*TP;
            float v = (t > 0 && t < Tq) ? __expf((ssv[i] - smx[r]) * 0.125f) : 0.f;
            g_E[(size_t)(row0 + r)*TP + t] = v;
        }
    }
    #undef STAGE_CHUNK
}

// ---------------------------------------------------------------------------
// K2 (attn): 512 blocks x 256 threads. Block = (8 rows, o-half of 32).
//   One warp per row: int4 dep gather (4 pos/lane) fused with row-sum.
// ---------------------------------------------------------------------------
__global__ void __launch_bounds__(256) attn_kernel(
        const int* __restrict__ dep,
        const float* __restrict__ bias,
        float* __restrict__ out) {
    __shared__ float sE[8*TP];
    __shared__ float sht[Sq*32];     // 16 KB
    __shared__ float sA[8*Sq];
    __shared__ float sden[8];

    int tid = threadIdx.x;
    int bx  = blockIdx.x;
    int rg  = bx >> 1, oh = bx & 1;
    int gr0 = rg * 8;
    int b   = gr0 >> 7;

    // prefetch h_trans half (128 rows x 32 floats)
    {
        const float* src = g_ht + ((size_t)b * Sq) * Oq + oh*32;
        for (int i = tid; i < Sq*8; i += 256) {
            int u = i >> 3, q = i & 7;
            cp16(&sht[u*32 + q*4], src + (size_t)u*Oq + q*4);
        }
        asm volatile("cp.async.commit_group;" ::: "memory");
    }
    for (int i = tid; i < 8*TP; i += 256) sE[i] = g_E[(size_t)gr0*TP + i];
    __syncthreads();

    int g = tid >> 5, lane = tid & 31;    // warp g = row g
    {
        int4 d = *(const int4*)&dep[(size_t)(gr0 + g)*Sq + lane*4];
        const float* Eg = sE + g*TP;
        float e0 = Eg[d.x], e1 = Eg[d.y], e2 = Eg[d.z], e3 = Eg[d.w];
        *(float4*)&sA[g*Sq + lane*4] = make_float4(e0, e1, e2, e3);
        float s = e0 + e1 + e2 + e3;
        #pragma unroll
        for (int off = 16; off; off >>= 1)
            s += __shfl_xor_sync(0xffffffffu, s, off);
        if (lane == 0) sden[g] = 1.0f / (s + 1e-6f);
    }
    asm volatile("cp.async.wait_group 0;" ::: "memory");
    __syncthreads();

    // matmul: one warp per row, lane = o within half
    const float* Ar = sA + g*Sq;
    float a = 0.f;
    #pragma unroll 8
    for (int u4 = 0; u4 < 32; u4++) {
        float4 av = *(const float4*)&Ar[u4*4];
        a += av.x * sht[(u4*4+0)*32 + lane]
           + av.y * sht[(u4*4+1)*32 + lane]
           + av.z * sht[(u4*4+2)*32 + lane]
           + av.w * sht[(u4*4+3)*32 + lane];
    }
    float v = a * sden[g] + bias[oh*32 + lane];
    out[(size_t)(gr0 + g)*Oq + oh*32 + lane] = fmaxf(v, 0.f);
}

// ---------------------------------------------------------------------------
// Inputs: h, dep_table, W1, b1, W2, b2, Wg, bg, bias, dep_type_matrix, aspect_mask
// ---------------------------------------------------------------------------
extern "C" void kernel_launch(void* const* d_in, const int* in_sizes, int n_in,
                              void* d_out, int out_size) {
    const float* h         = (const float*)d_in[0];
    const float* dep_table = (const float*)d_in[1];
    const float* W1        = (const float*)d_in[2];
    const float* b1        = (const float*)d_in[3];
    const float* W2        = (const float*)d_in[4];
    const float* b2        = (const float*)d_in[5];
    const float* Wg        = (const float*)d_in[6];
    const float* bg        = (const float*)d_in[7];
    const float* bias      = (const float*)d_in[8];
    const int*   dep       = (const int*)d_in[9];
    const unsigned char* mask = (const unsigned char*)d_in[10];

    const int gemm_smem = (4800 + 2*WBUF) * (int)sizeof(float);   // 54016 B
    cudaFuncSetAttribute(gemm_kernel,
                         cudaFuncAttributeMaxDynamicSharedMemorySize, gemm_smem);

    p1_kernel<<<75, 64>>>(dep_table, W1, b1, W2, b2);
    gemm_kernel<<<192, 256, gemm_smem>>>(h, Wg, bg, dep_table, mask);
    attn_kernel<<<512, 256>>>(dep, bias, (float*)d_out);
}